// round 13
// baseline (speedup 1.0000x reference)
#include <cuda_runtime.h>
#include <cuda_fp16.h>
#include <cstdint>

#define M_V 50000   // vocab
#define N_F 1000    // filters
#define K_D 300     // embedding dim
#define B_B 128
#define L_L 512

#define MP 50048    // padded A rows (391*128)
#define NP 1024     // padded B rows (4*256)
#define KPAIR 160   // padded K in half-pairs (320 halves, 10 chunks x 16)

#define SCALE_IN  128.0f              // 2^7 per operand (keeps lo normal-range)
#define SCALE_OUT (1.0f / 16384.0f)   // 2^-14 on scores

// scratch — referenced ONLY from device code (never as host-side kernel args!)
__device__ float g_S[(size_t)M_V * N_F];        // 200 MB (scaled by 2^14)
__device__ uint2 g_A2[(size_t)MP * KPAIR];      // 64 MB pre-split (h2,l2)
__device__ uint2 g_B2[(size_t)NP * KPAIR];      // 1.3 MB

#define LDP 20                    // uint2 row stride (16 pairs + 4 pad)
#define STAGE_U2 (384 * LDP)      // A rows 0..127, B rows 128..383
#define SMEM_BYTES (2 * STAGE_U2 * 8)   // 122880
#define NCHUNK 10

// ---------------------------------------------------------------------------
__device__ __forceinline__ uint32_t h2u(half2 h) {
    return *reinterpret_cast<const uint32_t*>(&h);
}

__device__ __forceinline__ void mma16(float* c, const uint32_t* a, const uint32_t* b) {
    asm volatile(
        "mma.sync.aligned.m16n8k16.row.col.f32.f16.f16.f32 "
        "{%0,%1,%2,%3}, {%4,%5,%6,%7}, {%8,%9}, {%0,%1,%2,%3};"
        : "+f"(c[0]), "+f"(c[1]), "+f"(c[2]), "+f"(c[3])
        : "r"(a[0]), "r"(a[1]), "r"(a[2]), "r"(a[3]), "r"(b[0]), "r"(b[1]));
}

#define CP16(sm_u32, gp) \
    asm volatile("cp.async.cg.shared.global [%0], [%1], 16;" :: "r"(sm_u32), "l"(gp))
#define CP_COMMIT() asm volatile("cp.async.commit_group;" ::: "memory")
#define CP_WAIT1()  asm volatile("cp.async.wait_group 1;" ::: "memory")

// split 4 floats (scaled 2^7) into two (hi2, lo2) uint2 pairs
__device__ __forceinline__ uint4 split4(float4 v) {
    float x0 = v.x * SCALE_IN, x1 = v.y * SCALE_IN;
    float x2 = v.z * SCALE_IN, x3 = v.w * SCALE_IN;
    half2 h01 = __floats2half2_rn(x0, x1);
    half2 h23 = __floats2half2_rn(x2, x3);
    float2 f01 = __half22float2(h01);
    float2 f23 = __half22float2(h23);
    half2 l01 = __floats2half2_rn(x0 - f01.x, x1 - f01.y);
    half2 l23 = __floats2half2_rn(x2 - f23.x, x3 - f23.y);
    return make_uint4(h2u(h01), h2u(l01), h2u(h23), h2u(l23));
}

// ===========================================================================
// Presplit: fp32 [rows x 300] -> pair-packed uint2 rows [KPAIR], value *2^7.
// Row/K padding zeroed. One thread per uint4 slot (floats 4s..4s+3).
// ===========================================================================
__global__ __launch_bounds__(256) void presplit_A(const float* __restrict__ src) {
    int idx = blockIdx.x * 256 + threadIdx.x;
    int row = idx / 80, s = idx - row * 80;
    if (row >= MP) return;
    float4 v = make_float4(0.f, 0.f, 0.f, 0.f);
    if (row < M_V && s < 75) v = *(const float4*)(src + (size_t)row * K_D + s * 4);
    *(uint4*)(g_A2 + (size_t)row * KPAIR + s * 2) = split4(v);
}

__global__ __launch_bounds__(256) void presplit_B(const float* __restrict__ src) {
    int idx = blockIdx.x * 256 + threadIdx.x;
    int row = idx / 80, s = idx - row * 80;
    if (row >= NP) return;
    float4 v = make_float4(0.f, 0.f, 0.f, 0.f);
    if (row < N_F && s < 75) v = *(const float4*)(src + (size_t)row * K_D + s * 4);
    *(uint4*)(g_B2 + (size_t)row * KPAIR + s * 2) = split4(v);
}

// ===========================================================================
// Phase 1: S = Ah.Bh + Ah.Bl + Al.Bh  via fp16 m16n8k16 mma.sync (NT)
// 128x256 CTA tile, 512 threads / 16 warps (2x8 warptiles of 64x32),
// BK=32 floats (10 chunks), pre-split operands, cp.async 2-stage staging.
// 16 warps in one CTA -> 4 warps/SMSP issue overlap; A traffic halved.
// ===========================================================================
__global__ __launch_bounds__(512) void gemm_fp16x3() {
    extern __shared__ uint2 sm[];
    uint32_t smb;
    asm("{ .reg .u64 t; cvta.to.shared.u64 t, %1; cvt.u32.u64 %0, t; }"
        : "=r"(smb) : "l"(sm));

    const int tid = threadIdx.x;
    const int wid = tid >> 5, lid = tid & 31;
    const int qid = lid >> 2, ql = lid & 3;
    const int m0 = blockIdx.y * 128, n0 = blockIdx.x * 256;
    const int wm = (wid >> 3) * 64;        // 0 or 64
    const int wn = (wid & 7) * 32;         // 0..224

    float acc[4][4][4];
#pragma unroll
    for (int mt = 0; mt < 4; mt++)
#pragma unroll
        for (int nt = 0; nt < 4; nt++)
#pragma unroll
            for (int j = 0; j < 4; j++) acc[mt][nt][j] = 0.f;

    // staging roles: tid<128 -> A row tid; tid in [128,384) -> B row tid-128.
    const bool stgA = tid < 128;
    const bool stgB = (tid >= 128) && (tid < 384);
    const int arow = tid & 127;
    const int brow = tid - 128;
    const uint4* gsrc =
        stgA ? (const uint4*)(g_A2 + (size_t)(m0 + arow) * KPAIR)
             : (const uint4*)(g_B2 + (size_t)(n0 + (stgB ? brow : 0)) * KPAIR);
    const uint32_t sdst =
        smb + (uint32_t)(((stgA ? arow : 128 + brow) * LDP) * 8);

#define ISSUE(c, st) do { \
        if (stgA || stgB) { \
            uint32_t so = sdst + (uint32_t)(st) * (STAGE_U2 * 8); \
            const uint4* g = gsrc + (c) * 8; \
            CP16(so,       g);     CP16(so + 16,  g + 1); \
            CP16(so + 32,  g + 2); CP16(so + 48,  g + 3); \
            CP16(so + 64,  g + 4); CP16(so + 80,  g + 5); \
            CP16(so + 96,  g + 6); CP16(so + 112, g + 7); \
        } \
        CP_COMMIT(); \
    } while (0)

    ISSUE(0, 0);
    ISSUE(1, 1);

    for (int c = 0; c < NCHUNK; c++) {
        CP_WAIT1();          // chunk c's group complete (tail keeps this honest)
        __syncthreads();

        const uint2* As = sm + (c & 1) * STAGE_U2;
        const uint2* Bs = As + 128 * LDP;

        // ---- compute: 2 x k16 steps ----
#pragma unroll
        for (int kk = 0; kk < 2; kk++) {
            const int pb = kk * 8;
            uint32_t bh[4][2], bl[4][2];
#pragma unroll
            for (int nt = 0; nt < 4; nt++) {
                const uint2* p = Bs + (wn + nt * 8 + qid) * LDP + pb + ql;
                uint2 b0 = p[0], b1 = p[4];
                bh[nt][0] = b0.x; bh[nt][1] = b1.x;
                bl[nt][0] = b0.y; bl[nt][1] = b1.y;
            }
#pragma unroll
            for (int mt = 0; mt < 4; mt++) {
                const uint2* pa = As + (wm + mt * 16 + qid) * LDP + pb + ql;
                uint2 a0 = pa[0], a1 = pa[8 * LDP];
                uint2 a2 = pa[4], a3 = pa[8 * LDP + 4];
                uint32_t ah[4] = {a0.x, a1.x, a2.x, a3.x};
                uint32_t al[4] = {a0.y, a1.y, a2.y, a3.y};
#pragma unroll
                for (int nt = 0; nt < 4; nt++) {
                    mma16(acc[mt][nt], ah, bh[nt]);   // hi*hi
                    mma16(acc[mt][nt], ah, bl[nt]);   // hi*lo
                    mma16(acc[mt][nt], al, bh[nt]);   // lo*hi
                }
            }
        }
        __syncthreads();     // all warps done reading stage (c&1) before refill
        if (c + 2 < NCHUNK) ISSUE(c + 2, c & 1);
        else                CP_COMMIT();   // empty group keeps wait_group 1 honest
    }

    // ---- epilogue (scores scaled by 2^14; phase 2 descales) ----
#pragma unroll
    for (int mt = 0; mt < 4; mt++) {
        int mlo = m0 + wm + mt * 16 + qid;
        int mhi = mlo + 8;
#pragma unroll
        for (int nt = 0; nt < 4; nt++) {
            int n = n0 + wn + nt * 8 + ql * 2;
            if (n < N_F) {
                if (mlo < M_V)
                    *(float2*)(g_S + (size_t)mlo * N_F + n) =
                        make_float2(acc[mt][nt][0], acc[mt][nt][1]);
                if (mhi < M_V)
                    *(float2*)(g_S + (size_t)mhi * N_F + n) =
                        make_float2(acc[mt][nt][2], acc[mt][nt][3]);
            }
        }
    }
}

// ===========================================================================
// Phase 2: per (b,f): first-index argmax over t of S[inp[b,t],f] (scaled:
// argmax invariant); val = relu(2^-14*max + conv_b[f]);
// contrib = val*(fc_w[1,f]-fc_w[0,f]); token[b,argmax] += contrib;
// token += fc_b[1]-fc_b[0]. Deterministic ordered gather.
// ===========================================================================
__global__ __launch_bounds__(1024) void reduce_scatter(
    const int* __restrict__ inp, const float* __restrict__ cb,
    const float* __restrict__ fcw, const float* __restrict__ fcb,
    float* __restrict__ out) {
    __shared__ int   sw[L_L];
    __shared__ int   sbt[N_F];
    __shared__ float sct[N_F];

    const int b = blockIdx.x;
    const int tid = threadIdx.x;

    if (tid < L_L) sw[tid] = inp[b * L_L + tid];
    __syncthreads();

    const int f = tid;
    if (f < N_F) {
        const float* Sf = g_S + f;
        float best = -3.4e38f;
        int bestt = 0;
        for (int t0 = 0; t0 < L_L; t0 += 8) {
            float vv[8];
#pragma unroll
            for (int j = 0; j < 8; j++)
                vv[j] = Sf[(size_t)sw[t0 + j] * N_F];
#pragma unroll
            for (int j = 0; j < 8; j++) {
                if (vv[j] > best) { best = vv[j]; bestt = t0 + j; }  // first idx
            }
        }
        float val = fmaxf(best * SCALE_OUT + cb[f], 0.f);  // descale, relu
        float contrib = val * (fcw[N_F + f] - fcw[f]);     // 0 when val==0
        sbt[f] = bestt;
        sct[f] = contrib;
    }
    __syncthreads();

    if (tid < L_L) {
        float accv = fcb[1] - fcb[0];
        for (int ff = 0; ff < N_F; ff++) {
            if (sbt[ff] == tid) accv += sct[ff];
        }
        out[b * L_L + tid] = accv;
    }
}

extern "C" void kernel_launch(void* const* d_in, const int* in_sizes, int n_in,
                              void* d_out, int out_size) {
    const int*   inp    = (const int*)d_in[0];
    const float* emb    = (const float*)d_in[1];
    const float* conv_w = (const float*)d_in[2];   // [1000,1,300] contiguous
    const float* conv_b = (const float*)d_in[3];
    const float* fc_w   = (const float*)d_in[4];   // [2,1000]
    const float* fc_b   = (const float*)d_in[5];
    float* out = (float*)d_out;

    static int smem_set = 0;
    if (!smem_set) {
        cudaFuncSetAttribute(gemm_fp16x3,
                             cudaFuncAttributeMaxDynamicSharedMemorySize,
                             SMEM_BYTES);
        smem_set = 1;
    }

    presplit_A<<<(MP * 80 + 255) / 256, 256>>>(emb);
    presplit_B<<<(NP * 80 + 255) / 256, 256>>>(conv_w);
    gemm_fp16x3<<<dim3(4, 391), 512, SMEM_BYTES>>>();
    reduce_scatter<<<B_B, 1024>>>(inp, conv_b, fc_w, fc_b, out);
}

// round 14
// speedup vs baseline: 1.0445x; 1.0445x over previous
#include <cuda_runtime.h>
#include <cuda_fp16.h>
#include <cstdint>

#define M_V 50000   // vocab
#define N_F 1000    // filters
#define K_D 300     // embedding dim
#define B_B 128
#define L_L 512

#define MP 50048    // padded A rows (391*128)
#define NP 1024     // padded B rows (8*128)
#define KPAIR 152   // K in half-pairs: 304 halves = 19 chunks x 16
#define KU4 76      // uint4 per row

#define SCALE_IN  128.0f              // 2^7 per operand (keeps lo normal-range)
#define SCALE_OUT (1.0f / 16384.0f)   // 2^-14 on scores

// scratch — referenced ONLY from device code (never as host-side kernel args!)
__device__ float g_S[(size_t)M_V * N_F];        // 200 MB (scaled by 2^14)
__device__ uint2 g_A2[(size_t)MP * KPAIR];      // 61 MB pre-split (h2,l2)
__device__ uint2 g_B2[(size_t)NP * KPAIR];      // 1.2 MB

#define LDP 12                   // uint2 row stride (8 pairs + 4 pad) - R9-proven
#define STAGE_U2 (256 * LDP)     // A rows 0..127, B rows 128..255 = 3072 uint2
#define NCHUNK 19

// ---------------------------------------------------------------------------
__device__ __forceinline__ uint32_t h2u(half2 h) {
    return *reinterpret_cast<const uint32_t*>(&h);
}

__device__ __forceinline__ void mma16(float* c, const uint32_t* a, const uint32_t* b) {
    asm volatile(
        "mma.sync.aligned.m16n8k16.row.col.f32.f16.f16.f32 "
        "{%0,%1,%2,%3}, {%4,%5,%6,%7}, {%8,%9}, {%0,%1,%2,%3};"
        : "+f"(c[0]), "+f"(c[1]), "+f"(c[2]), "+f"(c[3])
        : "r"(a[0]), "r"(a[1]), "r"(a[2]), "r"(a[3]), "r"(b[0]), "r"(b[1]));
}

// split 4 floats (scaled 2^7) into two (hi2, lo2) uint2 pairs
__device__ __forceinline__ uint4 split4(float4 v) {
    float x0 = v.x * SCALE_IN, x1 = v.y * SCALE_IN;
    float x2 = v.z * SCALE_IN, x3 = v.w * SCALE_IN;
    half2 h01 = __floats2half2_rn(x0, x1);
    half2 h23 = __floats2half2_rn(x2, x3);
    float2 f01 = __half22float2(h01);
    float2 f23 = __half22float2(h23);
    half2 l01 = __floats2half2_rn(x0 - f01.x, x1 - f01.y);
    half2 l23 = __floats2half2_rn(x2 - f23.x, x3 - f23.y);
    return make_uint4(h2u(h01), h2u(l01), h2u(h23), h2u(l23));
}

// ===========================================================================
// Presplit: fp32 [rows x 300] -> pair-packed uint2 rows [KPAIR], value *2^7.
// uint2 q = (h2(x2q,x2q+1), l2(x2q,x2q+1)). Row/K padding zeroed.
// One thread per uint4 slot s (floats 4s..4s+3), 76 slots per row.
// ===========================================================================
__global__ __launch_bounds__(256) void presplit_A(const float* __restrict__ src) {
    int idx = blockIdx.x * 256 + threadIdx.x;
    int row = idx / KU4, s = idx - row * KU4;
    if (row >= MP) return;
    float4 v = make_float4(0.f, 0.f, 0.f, 0.f);
    if (row < M_V && s < 75) v = *(const float4*)(src + (size_t)row * K_D + s * 4);
    *(uint4*)(g_A2 + (size_t)row * KPAIR + s * 2) = split4(v);
}

__global__ __launch_bounds__(256) void presplit_B(const float* __restrict__ src) {
    int idx = blockIdx.x * 256 + threadIdx.x;
    int row = idx / KU4, s = idx - row * KU4;
    if (row >= NP) return;
    float4 v = make_float4(0.f, 0.f, 0.f, 0.f);
    if (row < N_F && s < 75) v = *(const float4*)(src + (size_t)row * K_D + s * 4);
    *(uint4*)(g_B2 + (size_t)row * KPAIR + s * 2) = split4(v);
}

// ===========================================================================
// Phase 1: S = Ah.Bh + Ah.Bl + Al.Bh  via fp16 m16n8k16 mma.sync (NT)
// R9-proven skeleton: 128x128 CTA tile, BK=16 floats (19 chunks), 8 warps
// (64x32 warptile), LDP=12 layout, register-prefetch double buffering.
// ONLY change vs R9: operands are pre-split in global (plain uint4 copy
// staging; no cvts in loop; A DRAM traffic halved).
// ===========================================================================
__global__ __launch_bounds__(256) void gemm_fp16x3() {
    __shared__ uint2 sm[2 * STAGE_U2];   // 49152 bytes

    const int tid = threadIdx.x;
    const int wid = tid >> 5, lid = tid & 31;
    const int qid = lid >> 2, ql = lid & 3;
    const int m0 = blockIdx.y * 128, n0 = blockIdx.x * 128;
    const int wm = (wid >> 2) * 64, wn = (wid & 3) * 32;

    float acc[4][4][4];
#pragma unroll
    for (int mt = 0; mt < 4; mt++)
#pragma unroll
        for (int nt = 0; nt < 4; nt++)
#pragma unroll
            for (int j = 0; j < 4; j++) acc[mt][nt][j] = 0.f;

    // staging: row = tid>>1 (0..127), half = tid&1 -> uint4 slots {2h, 2h+1}
    // of the chunk. STS pattern: byte row*96 + half*32 + j*16 (2-way max).
    const int row_st = tid >> 1, half = tid & 1;
    const uint4* gA = (const uint4*)(g_A2 + (size_t)(m0 + row_st) * KPAIR) + half * 2;
    const uint4* gB = (const uint4*)(g_B2 + (size_t)(n0 + row_st) * KPAIR) + half * 2;
    uint2* sA = sm + row_st * LDP + half * 4;            // + stage offset
    uint2* sB = sA + 128 * LDP;

    uint4 stgA[2], stgB[2];

    // ---- prologue: load chunk 0, stage into buffer 0 ----
#pragma unroll
    for (int j = 0; j < 2; j++) { stgA[j] = gA[j]; stgB[j] = gB[j]; }
#pragma unroll
    for (int j = 0; j < 2; j++) {
        *(uint4*)(sA + j * 2) = stgA[j];
        *(uint4*)(sB + j * 2) = stgB[j];
    }
    __syncthreads();

    for (int c = 0; c < NCHUNK; c++) {
        const uint2* As = sm + (c & 1) * STAGE_U2;
        const uint2* Bs = As + 128 * LDP;
        const bool more = (c + 1 < NCHUNK);

        // prefetch next chunk into registers (latency hidden by MMAs)
        if (more) {
            const uint4* ga = gA + (c + 1) * 4;
            const uint4* gb = gB + (c + 1) * 4;
#pragma unroll
            for (int j = 0; j < 2; j++) { stgA[j] = ga[j]; stgB[j] = gb[j]; }
        }

        // ---- compute: one m16n8k16 step per (mt,nt) per pass ----
        uint32_t bh[4][2], bl[4][2];
#pragma unroll
        for (int nt = 0; nt < 4; nt++) {
            const uint2* p = Bs + (wn + nt * 8 + qid) * LDP + ql;
            uint2 b0 = p[0], b1 = p[4];      // pairs ql, ql+4
            bh[nt][0] = b0.x; bh[nt][1] = b1.x;
            bl[nt][0] = b0.y; bl[nt][1] = b1.y;
        }
#pragma unroll
        for (int mt = 0; mt < 4; mt++) {
            const uint2* pa = As + (wm + mt * 16 + qid) * LDP + ql;
            uint2 a0 = pa[0], a1 = pa[8 * LDP];
            uint2 a2 = pa[4], a3 = pa[8 * LDP + 4];
            uint32_t ah[4] = {a0.x, a1.x, a2.x, a3.x};
            uint32_t al[4] = {a0.y, a1.y, a2.y, a3.y};
#pragma unroll
            for (int nt = 0; nt < 4; nt++) {
                mma16(acc[mt][nt], ah, bh[nt]);   // hi*hi
                mma16(acc[mt][nt], ah, bl[nt]);   // hi*lo
                mma16(acc[mt][nt], al, bh[nt]);   // lo*hi
            }
        }

        // ---- store prefetched chunk into the other stage ----
        if (more) {
            uint2* dA = sA + ((c + 1) & 1) * STAGE_U2;
            uint2* dB = sB + ((c + 1) & 1) * STAGE_U2;
#pragma unroll
            for (int j = 0; j < 2; j++) {
                *(uint4*)(dA + j * 2) = stgA[j];
                *(uint4*)(dB + j * 2) = stgB[j];
            }
        }
        __syncthreads();
    }

    // ---- epilogue (scores scaled by 2^14; phase 2 descales) ----
#pragma unroll
    for (int mt = 0; mt < 4; mt++) {
        int mlo = m0 + wm + mt * 16 + qid;
        int mhi = mlo + 8;
#pragma unroll
        for (int nt = 0; nt < 4; nt++) {
            int n = n0 + wn + nt * 8 + ql * 2;
            if (n < N_F) {
                if (mlo < M_V)
                    *(float2*)(g_S + (size_t)mlo * N_F + n) =
                        make_float2(acc[mt][nt][0], acc[mt][nt][1]);
                if (mhi < M_V)
                    *(float2*)(g_S + (size_t)mhi * N_F + n) =
                        make_float2(acc[mt][nt][2], acc[mt][nt][3]);
            }
        }
    }
}

// ===========================================================================
// Phase 2: per (b,f): first-index argmax over t of S[inp[b,t],f] (scaled:
// argmax invariant); val = relu(2^-14*max + conv_b[f]);
// contrib = val*(fc_w[1,f]-fc_w[0,f]); token[b,argmax] += contrib;
// token += fc_b[1]-fc_b[0]. Deterministic ordered gather.
// ===========================================================================
__global__ __launch_bounds__(1024) void reduce_scatter(
    const int* __restrict__ inp, const float* __restrict__ cb,
    const float* __restrict__ fcw, const float* __restrict__ fcb,
    float* __restrict__ out) {
    __shared__ int   sw[L_L];
    __shared__ int   sbt[N_F];
    __shared__ float sct[N_F];

    const int b = blockIdx.x;
    const int tid = threadIdx.x;

    if (tid < L_L) sw[tid] = inp[b * L_L + tid];
    __syncthreads();

    const int f = tid;
    if (f < N_F) {
        const float* Sf = g_S + f;
        float best = -3.4e38f;
        int bestt = 0;
        for (int t0 = 0; t0 < L_L; t0 += 8) {
            float vv[8];
#pragma unroll
            for (int j = 0; j < 8; j++)
                vv[j] = Sf[(size_t)sw[t0 + j] * N_F];
#pragma unroll
            for (int j = 0; j < 8; j++) {
                if (vv[j] > best) { best = vv[j]; bestt = t0 + j; }  // first idx
            }
        }
        float val = fmaxf(best * SCALE_OUT + cb[f], 0.f);  // descale, relu
        float contrib = val * (fcw[N_F + f] - fcw[f]);     // 0 when val==0
        sbt[f] = bestt;
        sct[f] = contrib;
    }
    __syncthreads();

    if (tid < L_L) {
        float accv = fcb[1] - fcb[0];
        for (int ff = 0; ff < N_F; ff++) {
            if (sbt[ff] == tid) accv += sct[ff];
        }
        out[b * L_L + tid] = accv;
    }
}

extern "C" void kernel_launch(void* const* d_in, const int* in_sizes, int n_in,
                              void* d_out, int out_size) {
    const int*   inp    = (const int*)d_in[0];
    const float* emb    = (const float*)d_in[1];
    const float* conv_w = (const float*)d_in[2];   // [1000,1,300] contiguous
    const float* conv_b = (const float*)d_in[3];
    const float* fc_w   = (const float*)d_in[4];   // [2,1000]
    const float* fc_b   = (const float*)d_in[5];
    float* out = (float*)d_out;

    presplit_A<<<(MP * KU4 + 255) / 256, 256>>>(emb);
    presplit_B<<<(NP * KU4 + 255) / 256, 256>>>(conv_w);
    gemm_fp16x3<<<dim3(8, 391), 256>>>();
    reduce_scatter<<<B_B, 1024>>>(inp, conv_b, fc_w, fc_b, out);
}

// round 15
// speedup vs baseline: 1.2955x; 1.2403x over previous
#include <cuda_runtime.h>
#include <cuda_fp16.h>
#include <cstdint>

#define M_V 50000   // vocab
#define N_F 1000    // filters
#define K_D 300     // embedding dim
#define B_B 128
#define L_L 512

#define MP 50048    // padded A rows (391*128)
#define NP 1024     // padded B rows (8*128)
#define KPAIR 152   // K in half-pairs: 304 halves = 19 chunks x 16
#define KU4 76      // uint4 per row

#define SCALE_IN  128.0f              // 2^7 per operand (keeps lo normal-range)
#define SCALE_OUT (1.0f / 16384.0f)   // 2^-14 on scores

// scratch — referenced ONLY from device code (never as host-side kernel args!)
__device__ float g_S[(size_t)M_V * N_F];        // 200 MB (scaled by 2^14)
__device__ uint2 g_A2[(size_t)MP * KPAIR];      // 61 MB pre-split (h2,l2)
__device__ uint2 g_B2[(size_t)NP * KPAIR];      // 1.2 MB

#define LDP 12                   // uint2 row stride (8 pairs + 4 pad) - proven
#define STAGE_U2 (256 * LDP)     // A rows 0..127, B rows 128..255 = 3072 uint2
#define NCHUNK 19

// ---------------------------------------------------------------------------
__device__ __forceinline__ uint32_t h2u(half2 h) {
    return *reinterpret_cast<const uint32_t*>(&h);
}

__device__ __forceinline__ void mma16(float* c, const uint32_t* a, const uint32_t* b) {
    asm volatile(
        "mma.sync.aligned.m16n8k16.row.col.f32.f16.f16.f32 "
        "{%0,%1,%2,%3}, {%4,%5,%6,%7}, {%8,%9}, {%0,%1,%2,%3};"
        : "+f"(c[0]), "+f"(c[1]), "+f"(c[2]), "+f"(c[3])
        : "r"(a[0]), "r"(a[1]), "r"(a[2]), "r"(a[3]), "r"(b[0]), "r"(b[1]));
}

#define CP16(sm_u32, gp) \
    asm volatile("cp.async.cg.shared.global [%0], [%1], 16;" :: "r"(sm_u32), "l"(gp))
#define CP_COMMIT() asm volatile("cp.async.commit_group;" ::: "memory")
#define CP_WAIT0()  asm volatile("cp.async.wait_group 0;" ::: "memory")

// split 4 floats (scaled 2^7) into two (hi2, lo2) uint2 pairs
__device__ __forceinline__ uint4 split4(float4 v) {
    float x0 = v.x * SCALE_IN, x1 = v.y * SCALE_IN;
    float x2 = v.z * SCALE_IN, x3 = v.w * SCALE_IN;
    half2 h01 = __floats2half2_rn(x0, x1);
    half2 h23 = __floats2half2_rn(x2, x3);
    float2 f01 = __half22float2(h01);
    float2 f23 = __half22float2(h23);
    half2 l01 = __floats2half2_rn(x0 - f01.x, x1 - f01.y);
    half2 l23 = __floats2half2_rn(x2 - f23.x, x3 - f23.y);
    return make_uint4(h2u(h01), h2u(l01), h2u(h23), h2u(l23));
}

// ===========================================================================
// Presplit: fp32 [rows x 300] -> pair-packed uint2 rows [KPAIR], value *2^7.
// uint2 q = (h2(x2q,x2q+1), l2(x2q,x2q+1)). Row/K padding zeroed.
// ===========================================================================
__global__ __launch_bounds__(256) void presplit_A(const float* __restrict__ src) {
    int idx = blockIdx.x * 256 + threadIdx.x;
    int row = idx / KU4, s = idx - row * KU4;
    if (row >= MP) return;
    float4 v = make_float4(0.f, 0.f, 0.f, 0.f);
    if (row < M_V && s < 75) v = *(const float4*)(src + (size_t)row * K_D + s * 4);
    *(uint4*)(g_A2 + (size_t)row * KPAIR + s * 2) = split4(v);
}

__global__ __launch_bounds__(256) void presplit_B(const float* __restrict__ src) {
    int idx = blockIdx.x * 256 + threadIdx.x;
    int row = idx / KU4, s = idx - row * KU4;
    if (row >= NP) return;
    float4 v = make_float4(0.f, 0.f, 0.f, 0.f);
    if (row < N_F && s < 75) v = *(const float4*)(src + (size_t)row * K_D + s * 4);
    *(uint4*)(g_B2 + (size_t)row * KPAIR + s * 2) = split4(v);
}

// ===========================================================================
// Phase 1: S = Ah.Bh + Ah.Bl + Al.Bh  via fp16 m16n8k16 mma.sync (NT)
// 128x128 CTA tile, BK=16 (19 chunks), 8 warps (64x32 warptile), LDP=12,
// cp.async staging (zero staging regs) -> fits 2 CTAs/SM (launch_bounds 256,2)
// for 4 warps/SMSP latency hiding. One sync per chunk:
//   top: cp.async chunk c+1 -> stage (c+1)&1
//   compute stage c&1  (covers the async latency)
//   wait_group 0 + syncthreads
// ===========================================================================
__global__ __launch_bounds__(256, 2) void gemm_fp16x3() {
    __shared__ uint2 sm[2 * STAGE_U2];   // 49152 bytes
    uint32_t smb;
    asm("{ .reg .u64 t; cvta.to.shared.u64 t, %1; cvt.u32.u64 %0, t; }"
        : "=r"(smb) : "l"(sm));

    const int tid = threadIdx.x;
    const int wid = tid >> 5, lid = tid & 31;
    const int qid = lid >> 2, ql = lid & 3;
    const int m0 = blockIdx.y * 128, n0 = blockIdx.x * 128;
    const int wm = (wid >> 2) * 64, wn = (wid & 3) * 32;

    float acc[4][4][4];
#pragma unroll
    for (int mt = 0; mt < 4; mt++)
#pragma unroll
        for (int nt = 0; nt < 4; nt++)
#pragma unroll
            for (int j = 0; j < 4; j++) acc[mt][nt][j] = 0.f;

    // staging: row = tid>>1 (0..127), half = tid&1 -> 2 uint4 of A + 2 of B
    const int row_st = tid >> 1, half = tid & 1;
    const uint4* gA = (const uint4*)(g_A2 + (size_t)(m0 + row_st) * KPAIR) + half * 2;
    const uint4* gB = (const uint4*)(g_B2 + (size_t)(n0 + row_st) * KPAIR) + half * 2;
    const uint32_t sAb = smb + (uint32_t)(row_st * LDP + half * 4) * 8;
    const uint32_t sBb = sAb + 128 * LDP * 8;

#define ISSUE(c, st) do { \
        uint32_t so = (uint32_t)(st) * (STAGE_U2 * 8); \
        const uint4* ga = gA + (c) * 4; \
        const uint4* gb = gB + (c) * 4; \
        CP16(sAb + so,      ga); CP16(sAb + so + 16, ga + 1); \
        CP16(sBb + so,      gb); CP16(sBb + so + 16, gb + 1); \
        CP_COMMIT(); \
    } while (0)

    // ---- prologue: chunk 0 into stage 0 ----
    ISSUE(0, 0);
    CP_WAIT0();
    __syncthreads();

    for (int c = 0; c < NCHUNK; c++) {
        const bool more = (c + 1 < NCHUNK);
        if (more) ISSUE(c + 1, (c + 1) & 1);

        const uint2* As = sm + (c & 1) * STAGE_U2;
        const uint2* Bs = As + 128 * LDP;

        // ---- compute: one m16n8k16 per (mt,nt) per pass ----
        uint32_t bh[4][2], bl[4][2];
#pragma unroll
        for (int nt = 0; nt < 4; nt++) {
            const uint2* p = Bs + (wn + nt * 8 + qid) * LDP + ql;
            uint2 b0 = p[0], b1 = p[4];      // pairs ql, ql+4
            bh[nt][0] = b0.x; bh[nt][1] = b1.x;
            bl[nt][0] = b0.y; bl[nt][1] = b1.y;
        }
#pragma unroll
        for (int mt = 0; mt < 4; mt++) {
            const uint2* pa = As + (wm + mt * 16 + qid) * LDP + ql;
            uint2 a0 = pa[0], a1 = pa[8 * LDP];
            uint2 a2 = pa[4], a3 = pa[8 * LDP + 4];
            uint32_t ah[4] = {a0.x, a1.x, a2.x, a3.x};
            uint32_t al[4] = {a0.y, a1.y, a2.y, a3.y};
#pragma unroll
            for (int nt = 0; nt < 4; nt++) {
                mma16(acc[mt][nt], ah, bh[nt]);   // hi*hi
                mma16(acc[mt][nt], ah, bl[nt]);   // hi*lo
                mma16(acc[mt][nt], al, bh[nt]);   // lo*hi
            }
        }

        if (more) {
            CP_WAIT0();       // chunk c+1 landed
            __syncthreads();  // stage (c&1) free for reuse; (c+1)&1 visible
        }
    }

    // ---- epilogue (scores scaled by 2^14; phase 2 descales) ----
#pragma unroll
    for (int mt = 0; mt < 4; mt++) {
        int mlo = m0 + wm + mt * 16 + qid;
        int mhi = mlo + 8;
#pragma unroll
        for (int nt = 0; nt < 4; nt++) {
            int n = n0 + wn + nt * 8 + ql * 2;
            if (n < N_F) {
                if (mlo < M_V)
                    *(float2*)(g_S + (size_t)mlo * N_F + n) =
                        make_float2(acc[mt][nt][0], acc[mt][nt][1]);
                if (mhi < M_V)
                    *(float2*)(g_S + (size_t)mhi * N_F + n) =
                        make_float2(acc[mt][nt][2], acc[mt][nt][3]);
            }
        }
    }
}

// ===========================================================================
// Phase 2: per (b,f): first-index argmax over t of S[inp[b,t],f] (scaled:
// argmax invariant); val = relu(2^-14*max + conv_b[f]);
// contrib = val*(fc_w[1,f]-fc_w[0,f]); token[b,argmax] += contrib;
// token += fc_b[1]-fc_b[0]. Deterministic ordered gather.
// ===========================================================================
__global__ __launch_bounds__(1024) void reduce_scatter(
    const int* __restrict__ inp, const float* __restrict__ cb,
    const float* __restrict__ fcw, const float* __restrict__ fcb,
    float* __restrict__ out) {
    __shared__ int   sw[L_L];
    __shared__ int   sbt[N_F];
    __shared__ float sct[N_F];

    const int b = blockIdx.x;
    const int tid = threadIdx.x;

    if (tid < L_L) sw[tid] = inp[b * L_L + tid];
    __syncthreads();

    const int f = tid;
    if (f < N_F) {
        const float* Sf = g_S + f;
        float best = -3.4e38f;
        int bestt = 0;
        for (int t0 = 0; t0 < L_L; t0 += 8) {
            float vv[8];
#pragma unroll
            for (int j = 0; j < 8; j++)
                vv[j] = Sf[(size_t)sw[t0 + j] * N_F];
#pragma unroll
            for (int j = 0; j < 8; j++) {
                if (vv[j] > best) { best = vv[j]; bestt = t0 + j; }  // first idx
            }
        }
        float val = fmaxf(best * SCALE_OUT + cb[f], 0.f);  // descale, relu
        float contrib = val * (fcw[N_F + f] - fcw[f]);     // 0 when val==0
        sbt[f] = bestt;
        sct[f] = contrib;
    }
    __syncthreads();

    if (tid < L_L) {
        float accv = fcb[1] - fcb[0];
        for (int ff = 0; ff < N_F; ff++) {
            if (sbt[ff] == tid) accv += sct[ff];
        }
        out[b * L_L + tid] = accv;
    }
}

extern "C" void kernel_launch(void* const* d_in, const int* in_sizes, int n_in,
                              void* d_out, int out_size) {
    const int*   inp    = (const int*)d_in[0];
    const float* emb    = (const float*)d_in[1];
    const float* conv_w = (const float*)d_in[2];   // [1000,1,300] contiguous
    const float* conv_b = (const float*)d_in[3];
    const float* fc_w   = (const float*)d_in[4];   // [2,1000]
    const float* fc_b   = (const float*)d_in[5];
    float* out = (float*)d_out;

    presplit_A<<<(MP * KU4 + 255) / 256, 256>>>(emb);
    presplit_B<<<(NP * KU4 + 255) / 256, 256>>>(conv_w);
    gemm_fp16x3<<<dim3(8, 391), 256>>>();
    reduce_scatter<<<B_B, 1024>>>(inp, conv_b, fc_w, fc_b, out);
}